// round 5
// baseline (speedup 1.0000x reference)
#include <cuda_runtime.h>
#include <stdint.h>

#define TT 32
#define NB 4
#define FRAMES (TT*NB)

#define C0 128
#define H0 16
#define W0 16
#define C1 64
#define H1 31
#define W1 31
#define C2 32
#define H2 61
#define W2 61
#define C3 2
#define H3 121
#define W3 121

#define P0 (H0*W0)     // 256
#define P1 (H1*W1)     // 961
#define P2 (H2*W2)     // 3721
#define P3 (H3*W3)     // 14641

// ---- device scratch ----
__device__ uint8_t g_cnt0[FRAMES*P0*4];
__device__ uint8_t g_lst0[FRAMES*P0*4*32];
__device__ float   g_w1q[9*C0*C1];       // [tap][ci][lane*2 + half]; co = half*32+lane; x2 scaled
__device__ float   g_w2r[9*C1*C2];       // [tap][ci][co]
__device__ float   g_w3r[9*C2*C3];       // [tap][ci][co]
__device__ uint8_t g_cnt1[FRAMES*P1*2];
__device__ uint8_t g_lst1[FRAMES*P1*2*32];
__device__ uint8_t g_cnt2[FRAMES*P2];
__device__ uint8_t g_lst2[(size_t)FRAMES*P2*32];
__device__ int     g_cnt[3];

__global__ void k_zero() { if (threadIdx.x < 3) g_cnt[threadIdx.x] = 0; }

// ---- all weight rearrangement in one kernel ----
__global__ void k_wprepAll(const float* __restrict__ w1, const float* __restrict__ w2,
                           const float* __restrict__ w3) {
    int idx = blockIdx.x*256 + threadIdx.x;
    if (idx < 9*C0*C1) {
        int q  = idx & 63;
        int ci = (idx >> 6) & 127;
        int tap = idx >> 13;
        int co = (q & 1)*32 + (q >> 1);
        g_w1q[idx] = 2.0f * w1[(ci*C1 + co)*9 + tap];
    } else if (idx < 9*C0*C1 + 9*C1*C2) {
        int i = idx - 9*C0*C1;
        int co = i & 31;
        int ci = (i >> 5) & 63;
        int tap = i >> 11;
        g_w2r[i] = 2.0f * w2[(ci*C2 + co)*9 + tap];
    } else if (idx < 9*C0*C1 + 9*C1*C2 + 9*C2*C3) {
        int i = idx - (9*C0*C1 + 9*C1*C2);
        int co = i & 1;
        int ci = (i >> 1) & 31;
        int tap = i >> 6;
        g_w3r[i] = 2.0f * w3[(ci*C3 + co)*9 + tap];
    }
}

// ---- build layer-0 spike lists from input ----
__global__ void k_list0(const float* __restrict__ x) {
    const int lane = threadIdx.x & 31;
    const int gw = blockIdx.x*(blockDim.x>>5) + (threadIdx.x>>5);
    const int total = NB*P0*4;
    if (gw >= total) return;
    const int word = gw & 3;
    const int pix  = (gw >> 2) % P0;
    const int n    = gw / (4*P0);
    const int ci = word*32 + lane;
    const float4* xp = (const float4*)(x + (((size_t)n*C0 + ci)*P0 + pix)*TT);
    float4 v[8];
    #pragma unroll
    for (int q = 0; q < 8; q++) v[q] = xp[q];
    const uint32_t ltmask = (1u << lane) - 1u;
    #pragma unroll
    for (int t = 0; t < TT; t++) {
        float4 vv = v[t >> 2];
        float f = (t&3)==0 ? vv.x : (t&3)==1 ? vv.y : (t&3)==2 ? vv.z : vv.w;
        bool s = (f >= 0.5f);
        uint32_t bal = __ballot_sync(0xffffffffu, s);
        int li = ((t*NB+n)*P0 + pix)*4 + word;
        if (s) g_lst0[(size_t)li*32 + __popc(bal & ltmask)] = (uint8_t)lane;
        if (lane == 0) g_cnt0[li] = (uint8_t)__popc(bal);
    }
}

// ---- layer 1 fused conv+LIF: class-partitioned persistent blocks ----
// lane accumulates channels (lane) in acc0 and (lane+32) in acc1 via interleaved w1q.
__global__ void __launch_bounds__(1024)
k_fused1() {
    extern __shared__ float sW[];
    const int blk = blockIdx.x;
    int cls, first, nblk;
    if (blk < 18)      { cls = 0; first = 0;  nblk = 18; }
    else if (blk < 51) { cls = 1; first = 18; nblk = 33; }
    else if (blk < 84) { cls = 2; first = 51; nblk = 33; }
    else               { cls = 3; first = 84; nblk = 64; }
    const int PH = cls >> 1, PW = cls & 1;
    const int nh = PH + 1, nw = PW + 1;
    const int nt = nh*nw;
    for (int i = threadIdx.x; i < nt*C0*C1; i += 1024) {
        int ti = i >> 13;        // / (128*64)
        int r  = i & 8191;
        int kh = PH ? (ti/nw)*2 : 1;
        int kw = PW ? (ti%nw)*2 : 1;
        sW[i] = g_w1q[(kh*3+kw)*8192 + r];
    }
    __syncthreads();
    const int lane = threadIdx.x & 31;
    const int warp = threadIdx.x >> 5;
    const int ROWS = PH ? H0-1 : H0;
    const int COLS = PW ? W0-1 : W0;
    const int tasks = NB*ROWS*COLS;
    const uint32_t ltmask = (1u << lane) - 1u;
    for (int task = (blk-first)*32 + warp; task < tasks; task += nblk*32) {
        const int ocol = task % COLS;
        const int orow = (task / COLS) % ROWS;
        const int n    = task / (COLS*ROWS);
        int po[4];
        {
            int ih0 = PH ? orow+1 : orow;
            int iw0 = PW ? ocol+1 : ocol;
            po[0] = ih0*W0 + iw0;
            po[1] = ih0*W0 + ocol;           // (a=0,b=1) only if nw==2
            po[2] = orow*W0 + iw0;           // (a=1,b=0) only if nh==2
            po[3] = orow*W0 + ocol;
        }
        const int oh = PH ? 2*orow+1 : 2*orow;
        const int ow = PW ? 2*ocol+1 : 2*ocol;
        const int opix = oh*W1 + ow;
        float cur0=0.f, vol0=0.f, cur1=0.f, vol1=0.f;
        int spk = 0;
        for (int t = 0; t < TT; t++) {
            const int tn = t*NB + n;
            const int fb = tn*P0;
            float acc0 = 0.f, acc1 = 0.f;
            #pragma unroll
            for (int a = 0; a < 2; a++) {
                if (a >= nh) break;
                #pragma unroll
                for (int b = 0; b < 2; b++) {
                    if (b >= nw) break;
                    const int ti = a*nw + b;
                    const int pb = (fb + po[a*2+b])*4;
                    const uint32_t c4 = *(const uint32_t*)(g_cnt0 + pb);
                    #pragma unroll
                    for (int wo = 0; wo < 4; wo++) {
                        const int c = (c4 >> (wo*8)) & 0xFF;
                        const uint8_t* lp = g_lst0 + (size_t)(pb + wo)*32;
                        const float2* wb = (const float2*)(sW + (ti*C0 + wo*32)*C1) + lane;
                        int j = 0;
                        for (; j + 4 <= c; j += 4) {
                            uint32_t q = *(const uint32_t*)(lp + j);
                            float2 va = wb[((q      ) & 0xFF)*32];
                            float2 vb = wb[((q >>  8) & 0xFF)*32];
                            float2 vc = wb[((q >> 16) & 0xFF)*32];
                            float2 vd = wb[((q >> 24)       )*32];
                            acc0 += va.x; acc1 += va.y;
                            acc0 += vb.x; acc1 += vb.y;
                            acc0 += vc.x; acc1 += vc.y;
                            acc0 += vd.x; acc1 += vd.y;
                        }
                        for (; j < c; j++) {
                            float2 va = wb[lp[j]*32];
                            acc0 += va.x; acc1 += va.y;
                        }
                    }
                }
            }
            cur0 = 0.5f*cur0 + acc0; vol0 = 0.5f*vol0 + cur0;
            bool s0 = (vol0 >= 1.0f); vol0 = s0 ? 0.f : vol0;
            cur1 = 0.5f*cur1 + acc1; vol1 = 0.5f*vol1 + cur1;
            bool s1 = (vol1 >= 1.0f); vol1 = s1 ? 0.f : vol1;
            spk += (s0 ? 1 : 0) + (s1 ? 1 : 0);
            uint32_t b0 = __ballot_sync(0xffffffffu, s0);
            uint32_t b1 = __ballot_sync(0xffffffffu, s1);
            const int li = (tn*P1 + opix)*2;
            if (s0) g_lst1[(size_t)li*32 + __popc(b0 & ltmask)] = (uint8_t)lane;
            if (s1) g_lst1[((size_t)li+1)*32 + __popc(b1 & ltmask)] = (uint8_t)lane;
            if (lane == 0)
                *(uint16_t*)(g_cnt1 + li) = (uint16_t)(__popc(b0) | (__popc(b1) << 8));
        }
        spk = __reduce_add_sync(0xffffffffu, spk);
        if (lane == 0) atomicAdd(&g_cnt[0], spk);
    }
}

// ---- layer 2 fused conv+LIF: class-agnostic (all 9 taps in 72KB smem) ----
__global__ void __launch_bounds__(1024)
k_fused2() {
    extern __shared__ float sW[];
    for (int i = threadIdx.x; i < 9*C1*C2; i += 1024) sW[i] = g_w2r[i];
    __syncthreads();
    const int lane = threadIdx.x & 31;
    const int warp = threadIdx.x >> 5;
    const int tasks = NB*P2;
    const int nwarps = gridDim.x*32;
    const uint32_t ltmask = (1u << lane) - 1u;
    for (int task = blockIdx.x*32 + warp; task < tasks; task += nwarps) {
        const int ow = task % W2;
        const int oh = (task / W2) % H2;
        const int n  = task / (W2*H2);
        int ip[4], tb[4], ntap;
        {
            int khs[2], ihs[2], nh2; int kws[2], iws[2], nw2;
            if (oh & 1) { khs[0]=0; ihs[0]=(oh+1)>>1; khs[1]=2; ihs[1]=(oh-1)>>1; nh2=2; }
            else        { khs[0]=1; ihs[0]=oh>>1; nh2=1; }
            if (ow & 1) { kws[0]=0; iws[0]=(ow+1)>>1; kws[1]=2; iws[1]=(ow-1)>>1; nw2=2; }
            else        { kws[0]=1; iws[0]=ow>>1; nw2=1; }
            ntap = 0;
            for (int a = 0; a < nh2; a++)
                for (int b = 0; b < nw2; b++) {
                    ip[ntap] = ihs[a]*W1 + iws[b];
                    tb[ntap] = (khs[a]*3 + kws[b])*C1*C2;
                    ntap++;
                }
        }
        float cur = 0.f, vol = 0.f;
        int spk = 0;
        for (int t = 0; t < TT; t++) {
            const int tn = t*NB + n;
            const int fb = tn*P1;
            float acc = 0.f;
            #pragma unroll
            for (int k = 0; k < 4; k++) {
                if (k >= ntap) break;
                const int pb = (fb + ip[k])*2;
                const uint16_t c2 = *(const uint16_t*)(g_cnt1 + pb);
                #pragma unroll
                for (int wo = 0; wo < 2; wo++) {
                    const int c = (c2 >> (wo*8)) & 0xFF;
                    const uint8_t* lp = g_lst1 + (size_t)(pb + wo)*32;
                    const float* wb = sW + tb[k] + wo*32*C2 + lane;
                    int j = 0;
                    for (; j + 4 <= c; j += 4) {
                        uint32_t q = *(const uint32_t*)(lp + j);
                        acc += wb[((q      ) & 0xFF)*32];
                        acc += wb[((q >>  8) & 0xFF)*32];
                        acc += wb[((q >> 16) & 0xFF)*32];
                        acc += wb[((q >> 24)       )*32];
                    }
                    for (; j < c; j++) acc += wb[lp[j]*32];
                }
            }
            cur = 0.5f*cur + acc;
            vol = 0.5f*vol + cur;
            bool s = (vol >= 1.0f);
            vol = s ? 0.f : vol;
            spk += s ? 1 : 0;
            uint32_t bal = __ballot_sync(0xffffffffu, s);
            const int li = tn*P2 + (oh*W2 + ow);
            if (s) g_lst2[(size_t)li*32 + __popc(bal & ltmask)] = (uint8_t)lane;
            if (lane == 0) g_cnt2[li] = (uint8_t)__popc(bal);
        }
        spk = __reduce_add_sync(0xffffffffu, spk);
        if (lane == 0) atomicAdd(&g_cnt[1], spk);
    }
}

// ---- layer 3 fused conv+LIF: thread per (n, output pixel), writes final output ----
__global__ void k_fused3(float* __restrict__ out) {
    __shared__ float sW[9*C2*2];
    for (int i = threadIdx.x; i < 9*C2*2; i += blockDim.x) sW[i] = g_w3r[i];
    __syncthreads();
    const int idx = blockIdx.x*blockDim.x + threadIdx.x;
    if (idx >= NB*P3) return;
    const int ow = idx % W3;
    const int oh = (idx / W3) % H3;
    const int n  = idx / P3;
    int ip[4], tb[4], ntap;
    {
        int khs[2], ihs[2], nh2; int kws[2], iws[2], nw2;
        if (oh & 1) { khs[0]=0; ihs[0]=(oh+1)>>1; khs[1]=2; ihs[1]=(oh-1)>>1; nh2=2; }
        else        { khs[0]=1; ihs[0]=oh>>1; nh2=1; }
        if (ow & 1) { kws[0]=0; iws[0]=(ow+1)>>1; kws[1]=2; iws[1]=(ow-1)>>1; nw2=2; }
        else        { kws[0]=1; iws[0]=ow>>1; nw2=1; }
        ntap = 0;
        for (int a = 0; a < nh2; a++)
            for (int b = 0; b < nw2; b++) {
                ip[ntap] = ihs[a]*W2 + iws[b];
                tb[ntap] = (khs[a]*3 + kws[b])*C2;
                ntap++;
            }
    }
    float cur0=0.f, vol0=0.f, cur1=0.f, vol1=0.f;
    int cnt = 0;
    float res0[TT], res1[TT];
    #pragma unroll 4
    for (int t = 0; t < TT; t++) {
        const int tn = t*NB + n;
        const int fb = tn*P2;
        float a0 = 0.f, a1 = 0.f;
        #pragma unroll
        for (int k = 0; k < 4; k++) {
            if (k >= ntap) break;
            const int p = fb + ip[k];
            const int c = g_cnt2[p];
            const uint8_t* lp = g_lst2 + (size_t)p*32;
            const float2* wb = (const float2*)sW + tb[k];
            for (int j = 0; j < c; j++) {
                float2 v = wb[lp[j]];
                a0 += v.x; a1 += v.y;
            }
        }
        cur0 = 0.5f*cur0 + a0; vol0 = 0.5f*vol0 + cur0;
        cur1 = 0.5f*cur1 + a1; vol1 = 0.5f*vol1 + cur1;
        bool s0 = (vol0 >= 1.0f), s1 = (vol1 >= 1.0f);
        vol0 = s0 ? 0.f : vol0;  vol1 = s1 ? 0.f : vol1;
        res0[t] = s0 ? 1.0f : 0.0f;  res1[t] = s1 ? 1.0f : 0.0f;
        cnt += (s0 ? 1 : 0) + (s1 ? 1 : 0);
    }
    const int pix = oh*W3 + ow;
    float4* op0 = (float4*)(out + (((size_t)n*C3 + 0)*P3 + pix)*TT);
    float4* op1 = (float4*)(out + (((size_t)n*C3 + 1)*P3 + pix)*TT);
    #pragma unroll
    for (int q = 0; q < 8; q++) {
        op0[q] = make_float4(res0[4*q], res0[4*q+1], res0[4*q+2], res0[4*q+3]);
        op1[q] = make_float4(res1[4*q], res1[4*q+1], res1[4*q+2], res1[4*q+3]);
    }
    atomicAdd(&g_cnt[2], cnt);
}

__global__ void k_final(float* out, int off) {
    if (threadIdx.x == 0) {
        out[off+0] = (float)g_cnt[0] * (1.0f / (float)((size_t)NB*C1*P1*TT));
        out[off+1] = (float)g_cnt[1] * (1.0f / (float)((size_t)NB*C2*P2*TT));
        out[off+2] = (float)g_cnt[2] * (1.0f / (float)((size_t)NB*C3*P3*TT));
    }
}

extern "C" void kernel_launch(void* const* d_in, const int* in_sizes, int n_in,
                              void* d_out, int out_size) {
    const float* x  = (const float*)d_in[0];
    const float* w1 = (const float*)d_in[1];
    const float* w2 = (const float*)d_in[2];
    const float* w3 = (const float*)d_in[3];
    float* out = (float*)d_out;

    const int smem1 = 4*C0*C1*4;   // 131072 (max class: odd/odd, 4 taps)
    const int smem2 = 9*C1*C2*4;   // 73728
    cudaFuncSetAttribute((const void*)k_fused1,
                         cudaFuncAttributeMaxDynamicSharedMemorySize, smem1);
    cudaFuncSetAttribute((const void*)k_fused2,
                         cudaFuncAttributeMaxDynamicSharedMemorySize, smem2);

    k_zero<<<1, 32>>>();
    k_wprepAll<<<(9*C0*C1 + 9*C1*C2 + 9*C2*C3 + 255)/256, 256>>>(w1, w2, w3);
    k_list0<<<(NB*P0*4)/8, 256>>>(x);
    k_fused1<<<148, 1024, smem1>>>();
    k_fused2<<<296, 1024, smem2>>>();
    k_fused3<<<(NB*P3 + 255)/256, 256>>>(out);
    k_final<<<1, 32>>>(out, out_size - 3);
}

// round 6
// speedup vs baseline: 1.2412x; 1.2412x over previous
#include <cuda_runtime.h>
#include <stdint.h>

#define TT 32
#define NB 4
#define FRAMES (TT*NB)

#define C0 128
#define H0 16
#define W0 16
#define C1 64
#define H1 31
#define W1 31
#define C2 32
#define H2 61
#define W2 61
#define C3 2
#define H3 121
#define W3 121

#define P0 (H0*W0)     // 256
#define P1 (H1*W1)     // 961
#define P2 (H2*W2)     // 3721
#define P3 (H3*W3)     // 14641

// ---- device scratch ----
__device__ uint8_t g_cnt0[FRAMES*P0*4];
__device__ uint8_t g_lst0[FRAMES*P0*4*32];
__device__ float   g_w1q[9*C0*C1];       // [tap][ci][lane*2+half]; co = half*32+lane; x2 scaled
__device__ float   g_w2r[9*C1*C2];       // [tap][ci][co]
__device__ float   g_w3r[9*C2*C3];       // [tap][ci][co]
__device__ uint8_t g_cnt1[FRAMES*P1*2];
__device__ uint8_t g_lst1[FRAMES*P1*2*32];
__device__ uint8_t g_cnt2[FRAMES*P2];
__device__ uint8_t g_lst2[FRAMES*P2*32];
__device__ int     g_cnt[3];

__global__ void k_zero() { if (threadIdx.x < 3) g_cnt[threadIdx.x] = 0; }

// ---- all weight rearrangement in one kernel ----
__global__ void k_wprepAll(const float* __restrict__ w1, const float* __restrict__ w2,
                           const float* __restrict__ w3) {
    int idx = blockIdx.x*256 + threadIdx.x;
    if (idx < 9*C0*C1) {
        int q  = idx & 63;
        int ci = (idx >> 6) & 127;
        int tap = idx >> 13;
        int co = (q & 1)*32 + (q >> 1);
        g_w1q[idx] = 2.0f * w1[(ci*C1 + co)*9 + tap];
    } else if (idx < 9*C0*C1 + 9*C1*C2) {
        int i = idx - 9*C0*C1;
        int co = i & 31;
        int ci = (i >> 5) & 63;
        int tap = i >> 11;
        g_w2r[i] = 2.0f * w2[(ci*C2 + co)*9 + tap];
    } else if (idx < 9*C0*C1 + 9*C1*C2 + 9*C2*C3) {
        int i = idx - (9*C0*C1 + 9*C1*C2);
        int co = i & 1;
        int ci = (i >> 1) & 31;
        int tap = i >> 6;
        g_w3r[i] = 2.0f * w3[(ci*C3 + co)*9 + tap];
    }
}

// ---- build layer-0 spike lists from input ----
__global__ void k_list0(const float* __restrict__ x) {
    const int lane = threadIdx.x & 31;
    const int gw = blockIdx.x*(blockDim.x>>5) + (threadIdx.x>>5);
    const int total = NB*P0*4;
    if (gw >= total) return;
    const int word = gw & 3;
    const int pix  = (gw >> 2) % P0;
    const int n    = gw / (4*P0);
    const int ci = word*32 + lane;
    const float4* xp = (const float4*)(x + (((size_t)n*C0 + ci)*P0 + pix)*TT);
    float4 v[8];
    #pragma unroll
    for (int q = 0; q < 8; q++) v[q] = xp[q];
    const uint32_t ltmask = (1u << lane) - 1u;
    #pragma unroll
    for (int t = 0; t < TT; t++) {
        float4 vv = v[t >> 2];
        float f = (t&3)==0 ? vv.x : (t&3)==1 ? vv.y : (t&3)==2 ? vv.z : vv.w;
        bool s = (f >= 0.5f);
        uint32_t bal = __ballot_sync(0xffffffffu, s);
        int li = ((t*NB+n)*P0 + pix)*4 + word;
        if (s) g_lst0[li*32 + __popc(bal & ltmask)] = (uint8_t)lane;
        if (lane == 0) g_cnt0[li] = (uint8_t)__popc(bal);
    }
}

// ==== layer 1 fused conv+LIF body: fully compile-time tap structure ====
template<int PH, int PW>
__device__ __forceinline__ void body1(float* sW, int firstBlk, int nblk) {
    constexpr int NKH = PH ? 2 : 1;
    constexpr int NKW = PW ? 2 : 1;
    constexpr int NT = NKH*NKW;
    for (int i = threadIdx.x; i < NT*C0*C1; i += 1024) {
        int ti = i >> 13;
        int r  = i & 8191;
        int kh = PH ? (ti/NKW)*2 : 1;
        int kw = PW ? (ti%NKW)*2 : 1;
        sW[i] = g_w1q[(kh*3+kw)*8192 + r];
    }
    __syncthreads();
    const int lane = threadIdx.x & 31;
    const int warp = threadIdx.x >> 5;
    constexpr int ROWS = PH ? H0-1 : H0;
    constexpr int COLS = PW ? W0-1 : W0;
    const int tasks = NB*ROWS*COLS;
    const uint32_t ltmask = (1u << lane) - 1u;
    for (int task = (blockIdx.x - firstBlk)*32 + warp; task < tasks; task += nblk*32) {
        const int ocol = task % COLS;
        const int orow = (task / COLS) % ROWS;
        const int n    = task / (COLS*ROWS);
        int po[NT];
        #pragma unroll
        for (int a = 0; a < NKH; a++) {
            const int ih = PH ? (a == 0 ? orow+1 : orow) : orow;
            #pragma unroll
            for (int b = 0; b < NKW; b++) {
                const int iw = PW ? (b == 0 ? ocol+1 : ocol) : ocol;
                po[a*NKW+b] = ih*W0 + iw;
            }
        }
        const int oh = PH ? 2*orow+1 : 2*orow;
        const int ow = PW ? 2*ocol+1 : 2*ocol;
        const int opix = oh*W1 + ow;
        float cur0=0.f, vol0=0.f, cur1=0.f, vol1=0.f;
        int spk = 0;
        #pragma unroll 1
        for (int t = 0; t < TT; t++) {
            const int fb = (t*NB + n)*P0;
            float acc0 = 0.f, acc1 = 0.f;
            #pragma unroll
            for (int ti = 0; ti < NT; ti++) {
                const int pb = (fb + po[ti])*4;
                const uint32_t c4 = *(const uint32_t*)(g_cnt0 + pb);
                #pragma unroll
                for (int wo = 0; wo < 4; wo++) {
                    const int c = (c4 >> (wo*8)) & 0xFF;
                    const uint8_t* lp = g_lst0 + (pb + wo)*32;
                    const float2* wb = (const float2*)(sW + (ti*C0 + wo*32)*C1) + lane;
                    int j = 0;
                    for (; j + 4 <= c; j += 4) {
                        uint32_t q = *(const uint32_t*)(lp + j);
                        float2 va = wb[((q      ) & 0xFF)*32];
                        float2 vb = wb[((q >>  8) & 0xFF)*32];
                        float2 vc = wb[((q >> 16) & 0xFF)*32];
                        float2 vd = wb[((q >> 24)       )*32];
                        acc0 += va.x; acc1 += va.y;
                        acc0 += vb.x; acc1 += vb.y;
                        acc0 += vc.x; acc1 += vc.y;
                        acc0 += vd.x; acc1 += vd.y;
                    }
                    for (; j < c; j++) {
                        float2 va = wb[lp[j]*32];
                        acc0 += va.x; acc1 += va.y;
                    }
                }
            }
            cur0 = 0.5f*cur0 + acc0; vol0 = 0.5f*vol0 + cur0;
            bool s0 = (vol0 >= 1.0f); vol0 = s0 ? 0.f : vol0;
            cur1 = 0.5f*cur1 + acc1; vol1 = 0.5f*vol1 + cur1;
            bool s1 = (vol1 >= 1.0f); vol1 = s1 ? 0.f : vol1;
            spk += (s0 ? 1 : 0) + (s1 ? 1 : 0);
            uint32_t b0 = __ballot_sync(0xffffffffu, s0);
            uint32_t b1 = __ballot_sync(0xffffffffu, s1);
            const int li = ((t*NB+n)*P1 + opix)*2;
            if (s0) g_lst1[li*32      + __popc(b0 & ltmask)] = (uint8_t)lane;
            if (s1) g_lst1[(li+1)*32  + __popc(b1 & ltmask)] = (uint8_t)lane;
            if (lane == 0)
                *(uint16_t*)(g_cnt1 + li) = (uint16_t)(__popc(b0) | (__popc(b1) << 8));
        }
        spk = __reduce_add_sync(0xffffffffu, spk);
        if (lane == 0) atomicAdd(&g_cnt[0], spk);
    }
}

__global__ void __launch_bounds__(1024)
k_fused1() {
    extern __shared__ float sW[];
    const int blk = blockIdx.x;
    if (blk < 18)      body1<0,0>(sW, 0,  18);
    else if (blk < 51) body1<0,1>(sW, 18, 33);
    else if (blk < 84) body1<1,0>(sW, 51, 33);
    else               body1<1,1>(sW, 84, 64);
}

// ==== layer 2 fused conv+LIF body ====
template<int PH, int PW>
__device__ __forceinline__ void body2(float* sW, int firstBlk, int nblk) {
    constexpr int NKH = PH ? 2 : 1;
    constexpr int NKW = PW ? 2 : 1;
    constexpr int NT = NKH*NKW;
    for (int i = threadIdx.x; i < NT*C1*C2; i += 1024) {
        int ti = i >> 11;
        int r  = i & 2047;
        int kh = PH ? (ti/NKW)*2 : 1;
        int kw = PW ? (ti%NKW)*2 : 1;
        sW[i] = g_w2r[(kh*3+kw)*2048 + r];
    }
    __syncthreads();
    const int lane = threadIdx.x & 31;
    const int warp = threadIdx.x >> 5;
    constexpr int ROWS = PH ? H1-1 : H1;
    constexpr int COLS = PW ? W1-1 : W1;
    const int tasks = NB*ROWS*COLS;
    const uint32_t ltmask = (1u << lane) - 1u;
    for (int task = (blockIdx.x - firstBlk)*32 + warp; task < tasks; task += nblk*32) {
        const int ocol = task % COLS;
        const int orow = (task / COLS) % ROWS;
        const int n    = task / (COLS*ROWS);
        int po[NT];
        #pragma unroll
        for (int a = 0; a < NKH; a++) {
            const int ih = PH ? (a == 0 ? orow+1 : orow) : orow;
            #pragma unroll
            for (int b = 0; b < NKW; b++) {
                const int iw = PW ? (b == 0 ? ocol+1 : ocol) : ocol;
                po[a*NKW+b] = ih*W1 + iw;
            }
        }
        const int oh = PH ? 2*orow+1 : 2*orow;
        const int ow = PW ? 2*ocol+1 : 2*ocol;
        const int opix = oh*W2 + ow;
        float cur = 0.f, vol = 0.f;
        int spk = 0;
        #pragma unroll 1
        for (int t = 0; t < TT; t++) {
            const int fb = (t*NB + n)*P1;
            float acc = 0.f;
            #pragma unroll
            for (int ti = 0; ti < NT; ti++) {
                const int pb = (fb + po[ti])*2;
                const uint16_t c2 = *(const uint16_t*)(g_cnt1 + pb);
                #pragma unroll
                for (int wo = 0; wo < 2; wo++) {
                    const int c = (c2 >> (wo*8)) & 0xFF;
                    const uint8_t* lp = g_lst1 + (pb + wo)*32;
                    const float* wb = sW + (ti*C1 + wo*32)*C2 + lane;
                    int j = 0;
                    for (; j + 4 <= c; j += 4) {
                        uint32_t q = *(const uint32_t*)(lp + j);
                        acc += wb[((q      ) & 0xFF)*32];
                        acc += wb[((q >>  8) & 0xFF)*32];
                        acc += wb[((q >> 16) & 0xFF)*32];
                        acc += wb[((q >> 24)       )*32];
                    }
                    for (; j < c; j++) acc += wb[lp[j]*32];
                }
            }
            cur = 0.5f*cur + acc;
            vol = 0.5f*vol + cur;
            bool s = (vol >= 1.0f);
            vol = s ? 0.f : vol;
            spk += s ? 1 : 0;
            uint32_t bal = __ballot_sync(0xffffffffu, s);
            const int li = (t*NB+n)*P2 + opix;
            if (s) g_lst2[li*32 + __popc(bal & ltmask)] = (uint8_t)lane;
            if (lane == 0) g_cnt2[li] = (uint8_t)__popc(bal);
        }
        spk = __reduce_add_sync(0xffffffffu, spk);
        if (lane == 0) atomicAdd(&g_cnt[1], spk);
    }
}

__global__ void __launch_bounds__(1024)
k_fused2() {
    extern __shared__ float sW[];
    const int blk = blockIdx.x;
    if (blk < 34)       body2<0,0>(sW, 0,   34);
    else if (blk < 100) body2<0,1>(sW, 34,  66);
    else if (blk < 167) body2<1,0>(sW, 100, 67);
    else                body2<1,1>(sW, 167, 129);
}

// ---- layer 3 fused conv+LIF: thread per (n, output pixel), writes final output ----
__global__ void k_fused3(float* __restrict__ out) {
    __shared__ float sW[9*C2*2];
    for (int i = threadIdx.x; i < 9*C2*2; i += blockDim.x) sW[i] = g_w3r[i];
    __syncthreads();
    const int idx = blockIdx.x*blockDim.x + threadIdx.x;
    if (idx >= NB*P3) return;
    const int ow = idx % W3;
    const int oh = (idx / W3) % H3;
    const int n  = idx / P3;
    int ip[4], tb[4], ntap;
    {
        int khs[2], ihs[2], nh2; int kws[2], iws[2], nw2;
        if (oh & 1) { khs[0]=0; ihs[0]=(oh+1)>>1; khs[1]=2; ihs[1]=(oh-1)>>1; nh2=2; }
        else        { khs[0]=1; ihs[0]=oh>>1; nh2=1; }
        if (ow & 1) { kws[0]=0; iws[0]=(ow+1)>>1; kws[1]=2; iws[1]=(ow-1)>>1; nw2=2; }
        else        { kws[0]=1; iws[0]=ow>>1; nw2=1; }
        ntap = 0;
        for (int a = 0; a < nh2; a++)
            for (int b = 0; b < nw2; b++) {
                ip[ntap] = ihs[a]*W2 + iws[b];
                tb[ntap] = (khs[a]*3 + kws[b])*C2;
                ntap++;
            }
    }
    float cur0=0.f, vol0=0.f, cur1=0.f, vol1=0.f;
    int cnt = 0;
    float res0[TT], res1[TT];
    #pragma unroll 4
    for (int t = 0; t < TT; t++) {
        const int fb = (t*NB + n)*P2;
        float a0 = 0.f, a1 = 0.f;
        #pragma unroll
        for (int k = 0; k < 4; k++) {
            if (k >= ntap) break;
            const int p = fb + ip[k];
            const int c = g_cnt2[p];
            const uint8_t* lp = g_lst2 + p*32;
            const float2* wb = (const float2*)sW + tb[k];
            for (int j = 0; j < c; j++) {
                float2 v = wb[lp[j]];
                a0 += v.x; a1 += v.y;
            }
        }
        cur0 = 0.5f*cur0 + a0; vol0 = 0.5f*vol0 + cur0;
        cur1 = 0.5f*cur1 + a1; vol1 = 0.5f*vol1 + cur1;
        bool s0 = (vol0 >= 1.0f), s1 = (vol1 >= 1.0f);
        vol0 = s0 ? 0.f : vol0;  vol1 = s1 ? 0.f : vol1;
        res0[t] = s0 ? 1.0f : 0.0f;  res1[t] = s1 ? 1.0f : 0.0f;
        cnt += (s0 ? 1 : 0) + (s1 ? 1 : 0);
    }
    const int pix = oh*W3 + ow;
    float4* op0 = (float4*)(out + (((size_t)n*C3 + 0)*P3 + pix)*TT);
    float4* op1 = (float4*)(out + (((size_t)n*C3 + 1)*P3 + pix)*TT);
    #pragma unroll
    for (int q = 0; q < 8; q++) {
        op0[q] = make_float4(res0[4*q], res0[4*q+1], res0[4*q+2], res0[4*q+3]);
        op1[q] = make_float4(res1[4*q], res1[4*q+1], res1[4*q+2], res1[4*q+3]);
    }
    cnt = __reduce_add_sync(0xffffffffu, cnt);
    if ((threadIdx.x & 31) == 0) atomicAdd(&g_cnt[2], cnt);
}

__global__ void k_final(float* out, int off) {
    if (threadIdx.x == 0) {
        out[off+0] = (float)g_cnt[0] * (1.0f / (float)((size_t)NB*C1*P1*TT));
        out[off+1] = (float)g_cnt[1] * (1.0f / (float)((size_t)NB*C2*P2*TT));
        out[off+2] = (float)g_cnt[2] * (1.0f / (float)((size_t)NB*C3*P3*TT));
    }
}

extern "C" void kernel_launch(void* const* d_in, const int* in_sizes, int n_in,
                              void* d_out, int out_size) {
    const float* x  = (const float*)d_in[0];
    const float* w1 = (const float*)d_in[1];
    const float* w2 = (const float*)d_in[2];
    const float* w3 = (const float*)d_in[3];
    float* out = (float*)d_out;

    const int smem1 = 4*C0*C1*4;   // 131072 (odd/odd class)
    const int smem2 = 4*C1*C2*4;   // 32768  (odd/odd class)
    cudaFuncSetAttribute((const void*)k_fused1,
                         cudaFuncAttributeMaxDynamicSharedMemorySize, smem1);
    cudaFuncSetAttribute((const void*)k_fused2,
                         cudaFuncAttributeMaxDynamicSharedMemorySize, smem2);

    k_zero<<<1, 32>>>();
    k_wprepAll<<<(9*C0*C1 + 9*C1*C2 + 9*C2*C3 + 255)/256, 256>>>(w1, w2, w3);
    k_list0<<<(NB*P0*4)/8, 256>>>(x);
    k_fused1<<<148, 1024, smem1>>>();
    k_fused2<<<296, 1024, smem2>>>();
    k_fused3<<<(NB*P3 + 255)/256, 256>>>(out);
    k_final<<<1, 32>>>(out, out_size - 3);
}

// round 7
// speedup vs baseline: 1.9527x; 1.5732x over previous
#include <cuda_runtime.h>
#include <stdint.h>

#define TT 32
#define NB 4
#define FRAMES (TT*NB)

#define C0 128
#define H0 16
#define W0 16
#define C1 64
#define H1 31
#define W1 31
#define C2 32
#define H2 61
#define W2 61
#define C3 2
#define H3 121
#define W3 121

#define P0 (H0*W0)     // 256
#define P1 (H1*W1)     // 961
#define P2 (H2*W2)     // 3721
#define P3 (H3*W3)     // 14641

// ---- device scratch ----
__device__ uint8_t g_cnt0[FRAMES*P0];                 // merged count per pixel
__device__ uint8_t g_lst0[FRAMES*P0*128];             // merged list, ci in [0,128)
__device__ float   g_w1r[9*C0*C1];                    // [tap][ci][co], x2 scaled
__device__ float   g_w2r[9*C1*C2];
__device__ float   g_w3r[9*C2*C3];
__device__ float   g_z1[(size_t)FRAMES*P1*C1];
__device__ uint8_t g_cnt1[FRAMES*P1*2];               // per-word counts (c0,c1)
__device__ uint8_t g_lst1[FRAMES*P1*64];              // two 32-entry segments
__device__ float   g_z2[(size_t)FRAMES*P2*C2];
__device__ uint8_t g_cnt2[FRAMES*P2];
__device__ uint8_t g_lst2[FRAMES*P2*32];
__device__ float   g_z3[(size_t)FRAMES*P3*C3];
__device__ int     g_cnt[3];

// ---- weight rearrangement (+ zero counters) ----
__global__ void k_wprepAll(const float* __restrict__ w1, const float* __restrict__ w2,
                           const float* __restrict__ w3) {
    int idx = blockIdx.x*256 + threadIdx.x;
    if (blockIdx.x == 0 && threadIdx.x < 3) g_cnt[threadIdx.x] = 0;
    if (idx < 9*C0*C1) {
        int co = idx & 63;
        int ci = (idx >> 6) & 127;
        int tap = idx >> 13;
        g_w1r[idx] = 2.0f * w1[(ci*C1 + co)*9 + tap];
    } else if (idx < 9*C0*C1 + 9*C1*C2) {
        int i = idx - 9*C0*C1;
        int co = i & 31;
        int ci = (i >> 5) & 63;
        int tap = i >> 11;
        g_w2r[i] = 2.0f * w2[(ci*C2 + co)*9 + tap];
    } else if (idx < 9*C0*C1 + 9*C1*C2 + 9*C2*C3) {
        int i = idx - (9*C0*C1 + 9*C1*C2);
        int co = i & 1;
        int ci = (i >> 1) & 31;
        int tap = i >> 6;
        g_w3r[i] = 2.0f * w3[(ci*C3 + co)*9 + tap];
    }
}

// ---- build merged layer-0 spike lists: block = 4 warps = one (n,pix) ----
__global__ void k_list0(const float* __restrict__ x) {
    __shared__ uint32_t scnt[4];
    const int lane = threadIdx.x & 31;
    const int word = threadIdx.x >> 5;
    const int pix = blockIdx.x % P0;
    const int n   = blockIdx.x / P0;
    const int ci  = word*32 + lane;
    const float4* xp = (const float4*)(x + (((size_t)n*C0 + ci)*P0 + pix)*TT);
    float4 v[8];
    #pragma unroll
    for (int q = 0; q < 8; q++) v[q] = xp[q];
    const uint32_t ltmask = (1u << lane) - 1u;
    #pragma unroll 1
    for (int t = 0; t < TT; t++) {
        float4 vv = v[t >> 2];
        float f = (t&3)==0 ? vv.x : (t&3)==1 ? vv.y : (t&3)==2 ? vv.z : vv.w;
        bool s = (f >= 0.5f);
        uint32_t bal = __ballot_sync(0xffffffffu, s);
        if (lane == 0) scnt[word] = __popc(bal);
        __syncthreads();
        int off = 0;
        if (word > 0) off += scnt[0];
        if (word > 1) off += scnt[1];
        if (word > 2) off += scnt[2];
        const int p = (t*NB + n)*P0 + pix;
        if (s) g_lst0[p*128 + off + __popc(bal & ltmask)] = (uint8_t)ci;
        if (threadIdx.x == 0)
            g_cnt0[p] = (uint8_t)(scnt[0] + scnt[1] + scnt[2] + scnt[3]);
        __syncthreads();
    }
}

#define EV1(I) { float2 v_ = wb[(I)*32]; acc0 += v_.x; acc1 += v_.y; }
#define EV2(I) { acc += wb[(I)*32]; }

// ==== layer 1 conv body (merged list, 64 couts via float2) ====
template<int PH, int PW>
__device__ __forceinline__ void conv1body(float* sW, int firstBlk, int nblk) {
    constexpr int NKH = PH ? 2 : 1;
    constexpr int NKW = PW ? 2 : 1;
    constexpr int NT = NKH*NKW;
    for (int i = threadIdx.x; i < NT*C0*C1; i += 1024) {
        int ti = i >> 13;
        int r  = i & 8191;
        int kh = PH ? (ti/NKW)*2 : 1;
        int kw = PW ? (ti%NKW)*2 : 1;
        sW[i] = g_w1r[(kh*3+kw)*8192 + r];
    }
    __syncthreads();
    const int lane = threadIdx.x & 31;
    const int warp = threadIdx.x >> 5;
    constexpr int ROWS = PH ? H0-1 : H0;
    constexpr int COLS = PW ? W0-1 : W0;
    const int tasks = FRAMES*ROWS*COLS;
    for (int task = (blockIdx.x - firstBlk)*32 + warp; task < tasks; task += nblk*32) {
        const int ocol = task % COLS;
        const int tmp  = task / COLS;
        const int orow = tmp % ROWS;
        const int tn   = tmp / ROWS;
        const int fb   = tn*P0;
        int po[NT];
        #pragma unroll
        for (int a = 0; a < NKH; a++) {
            const int ih = PH ? (a == 0 ? orow+1 : orow) : orow;
            #pragma unroll
            for (int b = 0; b < NKW; b++) {
                const int iw = PW ? (b == 0 ? ocol+1 : ocol) : ocol;
                po[a*NKW+b] = fb + ih*W0 + iw;
            }
        }
        float acc0 = 0.f, acc1 = 0.f;
        #pragma unroll
        for (int ti = 0; ti < NT; ti++) {
            const int p = po[ti];
            const int c = g_cnt0[p];
            const uint8_t* lp = g_lst0 + p*128;
            const float2* wb = (const float2*)(sW + ti*8192) + lane;
            int j = 0;
            for (; j + 8 <= c; j += 8) {
                uint2 q = *(const uint2*)(lp + j);
                EV1((q.x      ) & 0xFF) EV1((q.x >>  8) & 0xFF)
                EV1((q.x >> 16) & 0xFF) EV1((q.x >> 24)       )
                EV1((q.y      ) & 0xFF) EV1((q.y >>  8) & 0xFF)
                EV1((q.y >> 16) & 0xFF) EV1((q.y >> 24)       )
            }
            if (j + 4 <= c) {
                uint32_t q = *(const uint32_t*)(lp + j);
                EV1((q      ) & 0xFF) EV1((q >>  8) & 0xFF)
                EV1((q >> 16) & 0xFF) EV1((q >> 24)       )
                j += 4;
            }
            for (; j < c; j++) EV1(lp[j]);
        }
        const int oh = PH ? 2*orow+1 : 2*orow;
        const int ow = PW ? 2*ocol+1 : 2*ocol;
        *(float2*)(g_z1 + ((size_t)tn*P1 + oh*W1 + ow)*C1 + 2*lane) =
            make_float2(acc0, acc1);
    }
}

__global__ void __launch_bounds__(1024)
k_conv1a() {   // classes ee / eo / oe  (<= 64KB smem, 2 blocks/SM)
    extern __shared__ float sW[];
    const int blk = blockIdx.x;
    if (blk < 62)       conv1body<0,0>(sW, 0,   62);
    else if (blk < 179) conv1body<0,1>(sW, 62,  117);
    else                conv1body<1,0>(sW, 179, 117);
}
__global__ void __launch_bounds__(1024)
k_conv1b() {   // class oo (128KB smem)
    extern __shared__ float sW[];
    conv1body<1,1>(sW, 0, 148);
}

// ==== layer 2 conv body (2-segment lists) ====
template<int PH, int PW>
__device__ __forceinline__ void conv2body(float* sW, int firstBlk, int nblk) {
    constexpr int NKH = PH ? 2 : 1;
    constexpr int NKW = PW ? 2 : 1;
    constexpr int NT = NKH*NKW;
    for (int i = threadIdx.x; i < NT*C1*C2; i += 1024) {
        int ti = i >> 11;
        int r  = i & 2047;
        int kh = PH ? (ti/NKW)*2 : 1;
        int kw = PW ? (ti%NKW)*2 : 1;
        sW[i] = g_w2r[(kh*3+kw)*2048 + r];
    }
    __syncthreads();
    const int lane = threadIdx.x & 31;
    const int warp = threadIdx.x >> 5;
    constexpr int ROWS = PH ? H1-1 : H1;
    constexpr int COLS = PW ? W1-1 : W1;
    const int tasks = FRAMES*ROWS*COLS;
    for (int task = (blockIdx.x - firstBlk)*32 + warp; task < tasks; task += nblk*32) {
        const int ocol = task % COLS;
        const int tmp  = task / COLS;
        const int orow = tmp % ROWS;
        const int tn   = tmp / ROWS;
        const int fb   = tn*P1;
        int po[NT];
        #pragma unroll
        for (int a = 0; a < NKH; a++) {
            const int ih = PH ? (a == 0 ? orow+1 : orow) : orow;
            #pragma unroll
            for (int b = 0; b < NKW; b++) {
                const int iw = PW ? (b == 0 ? ocol+1 : ocol) : ocol;
                po[a*NKW+b] = fb + ih*W1 + iw;
            }
        }
        float acc = 0.f;
        #pragma unroll
        for (int ti = 0; ti < NT; ti++) {
            const int p = po[ti];
            const uint16_t cc = *(const uint16_t*)(g_cnt1 + p*2);
            const uint8_t* lp = g_lst1 + p*64;
            #pragma unroll
            for (int seg = 0; seg < 2; seg++) {
                const int c = (cc >> (seg*8)) & 0xFF;
                const float* wb = sW + (ti*C1 + seg*32)*C2 + lane;
                int j = 0;
                for (; j + 8 <= c; j += 8) {
                    uint2 q = *(const uint2*)(lp + j);
                    EV2((q.x      ) & 0xFF) EV2((q.x >>  8) & 0xFF)
                    EV2((q.x >> 16) & 0xFF) EV2((q.x >> 24)       )
                    EV2((q.y      ) & 0xFF) EV2((q.y >>  8) & 0xFF)
                    EV2((q.y >> 16) & 0xFF) EV2((q.y >> 24)       )
                }
                if (j + 4 <= c) {
                    uint32_t q = *(const uint32_t*)(lp + j);
                    EV2((q      ) & 0xFF) EV2((q >>  8) & 0xFF)
                    EV2((q >> 16) & 0xFF) EV2((q >> 24)       )
                    j += 4;
                }
                for (; j < c; j++) EV2(lp[j]);
                lp += 32;
            }
        }
        const int oh = PH ? 2*orow+1 : 2*orow;
        const int ow = PW ? 2*ocol+1 : 2*ocol;
        g_z2[((size_t)tn*P2 + oh*W2 + ow)*C2 + lane] = acc;
    }
}

__global__ void __launch_bounds__(1024)
k_conv2() {
    extern __shared__ float sW[];
    const int blk = blockIdx.x;
    if (blk < 34)       conv2body<0,0>(sW, 0,   34);
    else if (blk < 101) conv2body<0,1>(sW, 34,  67);
    else if (blk < 168) conv2body<1,0>(sW, 101, 67);
    else                conv2body<1,1>(sW, 168, 128);
}

// ---- LIF layer 1: thread per (n,pix,c); emits 2-segment lists ----
__global__ void k_lif1() {
    const int idx = blockIdx.x*blockDim.x + threadIdx.x;   // exact grid
    const int c   = idx % C1;
    const int pix = (idx / C1) % P1;
    const int n   = idx / (C1*P1);
    const int lane = threadIdx.x & 31;
    const int word = (idx >> 5) & 1;
    const uint32_t ltmask = (1u << lane) - 1u;
    float cur = 0.f, vol = 0.f;
    int cnt = 0;
    #pragma unroll
    for (int t = 0; t < TT; t++) {
        const int f = t*NB + n;
        float zv = g_z1[((size_t)f*P1 + pix)*C1 + c];
        cur = 0.5f*cur + zv;
        vol = 0.5f*vol + cur;
        bool s = (vol >= 1.0f);
        vol = s ? 0.f : vol;
        cnt += s ? 1 : 0;
        uint32_t bal = __ballot_sync(0xffffffffu, s);
        const int p = f*P1 + pix;
        if (s) g_lst1[p*64 + word*32 + __popc(bal & ltmask)] = (uint8_t)lane;
        if (lane == 0) g_cnt1[p*2 + word] = (uint8_t)__popc(bal);
    }
    cnt = __reduce_add_sync(0xffffffffu, cnt);
    if (lane == 0) atomicAdd(&g_cnt[0], cnt);
}

// ---- LIF layer 2 ----
__global__ void k_lif2() {
    const int idx = blockIdx.x*blockDim.x + threadIdx.x;
    const int total = NB*P2*C2;
    if (idx >= total) return;                 // total % 32 == 0
    const int c   = idx % C2;
    const int pix = (idx / C2) % P2;
    const int n   = idx / (C2*P2);
    const int lane = threadIdx.x & 31;
    const uint32_t ltmask = (1u << lane) - 1u;
    float cur = 0.f, vol = 0.f;
    int cnt = 0;
    #pragma unroll
    for (int t = 0; t < TT; t++) {
        const int f = t*NB + n;
        float zv = g_z2[((size_t)f*P2 + pix)*C2 + c];
        cur = 0.5f*cur + zv;
        vol = 0.5f*vol + cur;
        bool s = (vol >= 1.0f);
        vol = s ? 0.f : vol;
        cnt += s ? 1 : 0;
        uint32_t bal = __ballot_sync(0xffffffffu, s);
        const int p = f*P2 + pix;
        if (s) g_lst2[p*32 + __popc(bal & ltmask)] = (uint8_t)lane;
        if (lane == 0) g_cnt2[p] = (uint8_t)__popc(bal);
    }
    cnt = __reduce_add_sync(0xffffffffu, cnt);
    if (lane == 0) atomicAdd(&g_cnt[1], cnt);
}

// ---- layer 3 conv: thread per (frame, output pixel) ----
__global__ void k_conv3() {
    __shared__ float sW[9*C2*2];
    for (int i = threadIdx.x; i < 9*C2*2; i += blockDim.x) sW[i] = g_w3r[i];
    __syncthreads();
    int idx = blockIdx.x*blockDim.x + threadIdx.x;
    if (idx >= FRAMES*P3) return;
    int ow = idx % W3;
    int oh = (idx / W3) % H3;
    int tn = idx / P3;
    int khs[2], ihs[2], nh; int kws[2], iws[2], nw;
    if (oh & 1) { khs[0]=0; ihs[0]=(oh+1)>>1; khs[1]=2; ihs[1]=(oh-1)>>1; nh=2; }
    else        { khs[0]=1; ihs[0]=oh>>1; nh=1; }
    if (ow & 1) { kws[0]=0; iws[0]=(ow+1)>>1; kws[1]=2; iws[1]=(ow-1)>>1; nw=2; }
    else        { kws[0]=1; iws[0]=ow>>1; nw=1; }
    float a0 = 0.f, a1 = 0.f;
    for (int a = 0; a < nh; a++)
        for (int b = 0; b < nw; b++) {
            int p = tn*P2 + ihs[a]*W2 + iws[b];
            int c = g_cnt2[p];
            const uint8_t* lp = g_lst2 + p*32;
            const float2* wb = (const float2*)sW + (khs[a]*3 + kws[b])*C2;
            for (int j = 0; j < c; j++) {
                float2 v = wb[lp[j]];
                a0 += v.x; a1 += v.y;
            }
        }
    *(float2*)(g_z3 + (size_t)idx*2) = make_float2(a0, a1);
}

// ---- final LIF: writes output [N,C,H,W,T] ----
__global__ void k_lif3out(float* __restrict__ out) {
    const int idx = blockIdx.x*blockDim.x + threadIdx.x;
    if (idx >= NB*P3) return;
    const int pix = idx % P3;
    const int n   = idx / P3;
    const size_t base    = ((size_t)n*P3 + pix)*C3;
    const size_t tstride = (size_t)NB*P3*C3;
    float cur0=0.f, vol0=0.f, cur1=0.f, vol1=0.f;
    int cnt = 0;
    float res0[TT], res1[TT];
    #pragma unroll
    for (int t = 0; t < TT; t++) {
        float2 zv = *(const float2*)(g_z3 + (size_t)t*tstride + base);
        cur0 = 0.5f*cur0 + zv.x; vol0 = 0.5f*vol0 + cur0;
        cur1 = 0.5f*cur1 + zv.y; vol1 = 0.5f*vol1 + cur1;
        bool s0 = (vol0 >= 1.0f), s1 = (vol1 >= 1.0f);
        vol0 = s0 ? 0.f : vol0;  vol1 = s1 ? 0.f : vol1;
        res0[t] = s0 ? 1.0f : 0.0f;  res1[t] = s1 ? 1.0f : 0.0f;
        cnt += (s0 ? 1 : 0) + (s1 ? 1 : 0);
    }
    float4* op0 = (float4*)(out + (((size_t)n*C3 + 0)*P3 + pix)*TT);
    float4* op1 = (float4*)(out + (((size_t)n*C3 + 1)*P3 + pix)*TT);
    #pragma unroll
    for (int q = 0; q < 8; q++) {
        op0[q] = make_float4(res0[4*q], res0[4*q+1], res0[4*q+2], res0[4*q+3]);
        op1[q] = make_float4(res1[4*q], res1[4*q+1], res1[4*q+2], res1[4*q+3]);
    }
    atomicAdd(&g_cnt[2], cnt);
}

__global__ void k_final(float* out, int off) {
    if (threadIdx.x == 0) {
        out[off+0] = (float)g_cnt[0] * (1.0f / (float)((size_t)NB*C1*P1*TT));
        out[off+1] = (float)g_cnt[1] * (1.0f / (float)((size_t)NB*C2*P2*TT));
        out[off+2] = (float)g_cnt[2] * (1.0f / (float)((size_t)NB*C3*P3*TT));
    }
}

extern "C" void kernel_launch(void* const* d_in, const int* in_sizes, int n_in,
                              void* d_out, int out_size) {
    const float* x  = (const float*)d_in[0];
    const float* w1 = (const float*)d_in[1];
    const float* w2 = (const float*)d_in[2];
    const float* w3 = (const float*)d_in[3];
    float* out = (float*)d_out;

    const int smem1a = 2*C0*C1*4;   // 65536 (eo/oe classes; ee uses 32KB of it)
    const int smem1b = 4*C0*C1*4;   // 131072 (oo)
    const int smem2  = 4*C1*C2*4;   // 32768 (oo class max)
    cudaFuncSetAttribute((const void*)k_conv1a,
                         cudaFuncAttributeMaxDynamicSharedMemorySize, smem1a);
    cudaFuncSetAttribute((const void*)k_conv1b,
                         cudaFuncAttributeMaxDynamicSharedMemorySize, smem1b);

    k_wprepAll<<<(9*C0*C1 + 9*C1*C2 + 9*C2*C3 + 255)/256, 256>>>(w1, w2, w3);
    k_list0<<<NB*P0, 128>>>(x);
    k_conv1a<<<296, 1024, smem1a>>>();
    k_conv1b<<<148, 1024, smem1b>>>();
    k_lif1<<<(NB*P1*C1)/256, 256>>>();
    k_conv2<<<296, 1024, smem2>>>();
    k_lif2<<<(NB*P2*C2 + 255)/256, 256>>>();
    k_conv3<<<(FRAMES*P3 + 255)/256, 256>>>();
    k_lif3out<<<(NB*P3 + 255)/256, 256>>>(out);
    k_final<<<1, 32>>>(out, out_size - 3);
}

// round 8
// speedup vs baseline: 2.5406x; 1.3011x over previous
#include <cuda_runtime.h>
#include <stdint.h>

#define TT 32
#define NB 4
#define FRAMES (TT*NB)

#define C0 128
#define H0 16
#define W0 16
#define C1 64
#define H1 31
#define W1 31
#define C2 32
#define H2 61
#define W2 61
#define C3 2
#define H3 121
#define W3 121

#define P0 (H0*W0)     // 256
#define P1 (H1*W1)     // 961
#define P2 (H2*W2)     // 3721
#define P3 (H3*W3)     // 14641

typedef unsigned long long u64;

// ---- device scratch ----
__device__ uint8_t g_cnt0[FRAMES*P0];                 // merged count per pixel (0..128)
__device__ uint8_t g_lst0[FRAMES*P0*128];             // merged list, ci in [0,128)
__device__ float   g_w1r[9*C0*C1];                    // [tap][ci][co], x2 scaled
__device__ float   g_w2r[9*C1*C2];
__device__ float   g_w3r[9*C2*C3];
__device__ float   g_z1[(size_t)FRAMES*P1*C1];
__device__ uint8_t g_cnt1[FRAMES*P1];                 // merged count (0..64)
__device__ uint8_t g_lst1[FRAMES*P1*64];              // merged list, ci in [0,64)
__device__ float   g_z2[(size_t)FRAMES*P2*C2];
__device__ uint8_t g_cnt2[FRAMES*P2];
__device__ uint8_t g_lst2[FRAMES*P2*32];
__device__ float   g_z3[(size_t)FRAMES*P3*C3];
__device__ int     g_cnt[3];

#define ADD2(A, W) asm("add.rn.f32x2 %0, %0, %1;" : "+l"(A) : "l"(W))

// ---- merged prep: blocks [0,1024) build layer-0 lists; rest rearrange weights ----
__global__ void k_prep(const float* __restrict__ x, const float* __restrict__ w1,
                       const float* __restrict__ w2, const float* __restrict__ w3) {
    if (blockIdx.x >= NB*P0) {
        int idx = (blockIdx.x - NB*P0)*128 + threadIdx.x;
        if (idx < 3) g_cnt[idx] = 0;
        if (idx < 9*C0*C1) {
            int co = idx & 63;
            int ci = (idx >> 6) & 127;
            int tap = idx >> 13;
            g_w1r[idx] = 2.0f * w1[(ci*C1 + co)*9 + tap];
        } else if (idx < 9*C0*C1 + 9*C1*C2) {
            int i = idx - 9*C0*C1;
            int co = i & 31;
            int ci = (i >> 5) & 63;
            int tap = i >> 11;
            g_w2r[i] = 2.0f * w2[(ci*C2 + co)*9 + tap];
        } else if (idx < 9*C0*C1 + 9*C1*C2 + 9*C2*C3) {
            int i = idx - (9*C0*C1 + 9*C1*C2);
            int co = i & 1;
            int ci = (i >> 1) & 31;
            int tap = i >> 6;
            g_w3r[i] = 2.0f * w3[(ci*C3 + co)*9 + tap];
        }
        return;
    }
    // ---- list0: block = 4 warps = one (n,pix) ----
    __shared__ uint32_t scnt[4];
    const int lane = threadIdx.x & 31;
    const int word = threadIdx.x >> 5;
    const int pix = blockIdx.x % P0;
    const int n   = blockIdx.x / P0;
    const int ci  = word*32 + lane;
    const float4* xp = (const float4*)(x + (((size_t)n*C0 + ci)*P0 + pix)*TT);
    float4 v[8];
    #pragma unroll
    for (int q = 0; q < 8; q++) v[q] = xp[q];
    const uint32_t ltmask = (1u << lane) - 1u;
    #pragma unroll 1
    for (int t = 0; t < TT; t++) {
        float4 vv = v[t >> 2];
        float f = (t&3)==0 ? vv.x : (t&3)==1 ? vv.y : (t&3)==2 ? vv.z : vv.w;
        bool s = (f >= 0.5f);
        uint32_t bal = __ballot_sync(0xffffffffu, s);
        if (lane == 0) scnt[word] = __popc(bal);
        __syncthreads();
        int off = 0;
        if (word > 0) off += scnt[0];
        if (word > 1) off += scnt[1];
        if (word > 2) off += scnt[2];
        const int p = (t*NB + n)*P0 + pix;
        if (s) g_lst0[p*128 + off + __popc(bal & ltmask)] = (uint8_t)ci;
        if (threadIdx.x == 0)
            g_cnt0[p] = (uint8_t)(scnt[0] + scnt[1] + scnt[2] + scnt[3]);
        __syncthreads();
    }
}

#define EV1(I) { u64 w_ = wb[(I)*32]; ADD2(acc, w_); }
#define EV2(I) { acc += wb[(I)*32]; }

// ==== layer 1 conv body (merged list, 64 couts packed in f32x2) ====
template<int PH, int PW>
__device__ __forceinline__ void conv1body(float* sW, int firstBlk, int nblk) {
    constexpr int NKH = PH ? 2 : 1;
    constexpr int NKW = PW ? 2 : 1;
    constexpr int NT = NKH*NKW;
    for (int i = threadIdx.x; i < NT*C0*C1; i += 1024) {
        int ti = i >> 13;
        int r  = i & 8191;
        int kh = PH ? (ti/NKW)*2 : 1;
        int kw = PW ? (ti%NKW)*2 : 1;
        sW[i] = g_w1r[(kh*3+kw)*8192 + r];
    }
    __syncthreads();
    const int lane = threadIdx.x & 31;
    const int warp = threadIdx.x >> 5;
    constexpr int ROWS = PH ? H0-1 : H0;
    constexpr int COLS = PW ? W0-1 : W0;
    const int tasks = FRAMES*ROWS*COLS;
    for (int task = (blockIdx.x - firstBlk)*32 + warp; task < tasks; task += nblk*32) {
        const int ocol = task % COLS;
        const int tmp  = task / COLS;
        const int orow = tmp % ROWS;
        const int tn   = tmp / ROWS;
        const int fb   = tn*P0;
        int po[NT];
        #pragma unroll
        for (int a = 0; a < NKH; a++) {
            const int ih = PH ? (a == 0 ? orow+1 : orow) : orow;
            #pragma unroll
            for (int b = 0; b < NKW; b++) {
                const int iw = PW ? (b == 0 ? ocol+1 : ocol) : ocol;
                po[a*NKW+b] = fb + ih*W0 + iw;
            }
        }
        u64 acc = 0ull;   // packed (0.0f, 0.0f)
        #pragma unroll
        for (int ti = 0; ti < NT; ti++) {
            const int p = po[ti];
            const int c = g_cnt0[p];
            const uint8_t* lp = g_lst0 + p*128;
            const u64* wb = (const u64*)(sW + ti*8192) + lane;
            int j = 0;
            for (; j + 8 <= c; j += 8) {
                uint2 q = *(const uint2*)(lp + j);
                EV1((q.x      ) & 0xFF) EV1((q.x >>  8) & 0xFF)
                EV1((q.x >> 16) & 0xFF) EV1((q.x >> 24)       )
                EV1((q.y      ) & 0xFF) EV1((q.y >>  8) & 0xFF)
                EV1((q.y >> 16) & 0xFF) EV1((q.y >> 24)       )
            }
            if (j + 4 <= c) {
                uint32_t q = *(const uint32_t*)(lp + j);
                EV1((q      ) & 0xFF) EV1((q >>  8) & 0xFF)
                EV1((q >> 16) & 0xFF) EV1((q >> 24)       )
                j += 4;
            }
            for (; j < c; j++) EV1(lp[j]);
        }
        const int oh = PH ? 2*orow+1 : 2*orow;
        const int ow = PW ? 2*ocol+1 : 2*ocol;
        *(u64*)(g_z1 + ((size_t)tn*P1 + oh*W1 + ow)*C1 + 2*lane) = acc;
    }
}

__global__ void __launch_bounds__(1024)
k_conv1a() {   // classes ee / eo / oe  (<= 64KB smem, 2 blocks/SM)
    extern __shared__ float sW[];
    const int blk = blockIdx.x;
    if (blk < 62)       conv1body<0,0>(sW, 0,   62);
    else if (blk < 179) conv1body<0,1>(sW, 62,  117);
    else                conv1body<1,0>(sW, 179, 117);
}
__global__ void __launch_bounds__(1024)
k_conv1b() {   // class oo (128KB smem)
    extern __shared__ float sW[];
    conv1body<1,1>(sW, 0, 148);
}

// ==== layer 2 conv body (merged 64-entry lists) ====
template<int PH, int PW>
__device__ __forceinline__ void conv2body(float* sW, int firstBlk, int nblk) {
    constexpr int NKH = PH ? 2 : 1;
    constexpr int NKW = PW ? 2 : 1;
    constexpr int NT = NKH*NKW;
    for (int i = threadIdx.x; i < NT*C1*C2; i += 1024) {
        int ti = i >> 11;
        int r  = i & 2047;
        int kh = PH ? (ti/NKW)*2 : 1;
        int kw = PW ? (ti%NKW)*2 : 1;
        sW[i] = g_w2r[(kh*3+kw)*2048 + r];
    }
    __syncthreads();
    const int lane = threadIdx.x & 31;
    const int warp = threadIdx.x >> 5;
    constexpr int ROWS = PH ? H1-1 : H1;
    constexpr int COLS = PW ? W1-1 : W1;
    const int tasks = FRAMES*ROWS*COLS;
    for (int task = (blockIdx.x - firstBlk)*32 + warp; task < tasks; task += nblk*32) {
        const int ocol = task % COLS;
        const int tmp  = task / COLS;
        const int orow = tmp % ROWS;
        const int tn   = tmp / ROWS;
        const int fb   = tn*P1;
        int po[NT];
        #pragma unroll
        for (int a = 0; a < NKH; a++) {
            const int ih = PH ? (a == 0 ? orow+1 : orow) : orow;
            #pragma unroll
            for (int b = 0; b < NKW; b++) {
                const int iw = PW ? (b == 0 ? ocol+1 : ocol) : ocol;
                po[a*NKW+b] = fb + ih*W1 + iw;
            }
        }
        float acc = 0.f;
        #pragma unroll
        for (int ti = 0; ti < NT; ti++) {
            const int p = po[ti];
            const int c = g_cnt1[p];
            const uint8_t* lp = g_lst1 + p*64;
            const float* wb = sW + ti*2048 + lane;
            int j = 0;
            for (; j + 8 <= c; j += 8) {
                uint2 q = *(const uint2*)(lp + j);
                EV2((q.x      ) & 0xFF) EV2((q.x >>  8) & 0xFF)
                EV2((q.x >> 16) & 0xFF) EV2((q.x >> 24)       )
                EV2((q.y      ) & 0xFF) EV2((q.y >>  8) & 0xFF)
                EV2((q.y >> 16) & 0xFF) EV2((q.y >> 24)       )
            }
            if (j + 4 <= c) {
                uint32_t q = *(const uint32_t*)(lp + j);
                EV2((q      ) & 0xFF) EV2((q >>  8) & 0xFF)
                EV2((q >> 16) & 0xFF) EV2((q >> 24)       )
                j += 4;
            }
            for (; j < c; j++) EV2(lp[j]);
        }
        const int oh = PH ? 2*orow+1 : 2*orow;
        const int ow = PW ? 2*ocol+1 : 2*ocol;
        g_z2[((size_t)tn*P2 + oh*W2 + ow)*C2 + lane] = acc;
    }
}

__global__ void __launch_bounds__(1024)
k_conv2() {
    extern __shared__ float sW[];
    const int blk = blockIdx.x;
    if (blk < 34)       conv2body<0,0>(sW, 0,   34);
    else if (blk < 101) conv2body<0,1>(sW, 34,  67);
    else if (blk < 168) conv2body<1,0>(sW, 101, 67);
    else                conv2body<1,1>(sW, 168, 128);
}

// ---- LIF layer 1: warp per (n,pix), 2 channels per lane; merged list ----
__global__ void k_lif1() {
    const int gw = blockIdx.x*4 + (threadIdx.x >> 5);   // grid 961 x 4 warps = 3844 exact
    const int lane = threadIdx.x & 31;
    const int pix = gw % P1;
    const int n   = gw / P1;
    const uint32_t ltmask = (1u << lane) - 1u;
    float cur0=0.f, vol0=0.f, cur1=0.f, vol1=0.f;
    int cnt = 0;
    #pragma unroll 1
    for (int t = 0; t < TT; t++) {
        const int f = t*NB + n;
        const size_t zb = ((size_t)f*P1 + pix)*C1 + lane;
        float z0 = g_z1[zb];
        float z1v = g_z1[zb + 32];
        cur0 = 0.5f*cur0 + z0;  vol0 = 0.5f*vol0 + cur0;
        cur1 = 0.5f*cur1 + z1v; vol1 = 0.5f*vol1 + cur1;
        bool s0 = (vol0 >= 1.0f); vol0 = s0 ? 0.f : vol0;
        bool s1 = (vol1 >= 1.0f); vol1 = s1 ? 0.f : vol1;
        cnt += (s0 ? 1 : 0) + (s1 ? 1 : 0);
        uint32_t b0 = __ballot_sync(0xffffffffu, s0);
        uint32_t b1 = __ballot_sync(0xffffffffu, s1);
        const int p = f*P1 + pix;
        const int off = __popc(b0);
        if (s0) g_lst1[p*64 + __popc(b0 & ltmask)] = (uint8_t)lane;
        if (s1) g_lst1[p*64 + off + __popc(b1 & ltmask)] = (uint8_t)(32 + lane);
        if (lane == 0) g_cnt1[p] = (uint8_t)(off + __popc(b1));
    }
    cnt = __reduce_add_sync(0xffffffffu, cnt);
    if (lane == 0) atomicAdd(&g_cnt[0], cnt);
}

// ---- LIF layer 2 ----
__global__ void k_lif2() {
    const int idx = blockIdx.x*blockDim.x + threadIdx.x;
    const int total = NB*P2*C2;
    if (idx >= total) return;                 // total % 32 == 0 -> full warps exit together
    const int c   = idx % C2;
    const int pix = (idx / C2) % P2;
    const int n   = idx / (C2*P2);
    const int lane = threadIdx.x & 31;
    const uint32_t ltmask = (1u << lane) - 1u;
    float cur = 0.f, vol = 0.f;
    int cnt = 0;
    #pragma unroll
    for (int t = 0; t < TT; t++) {
        const int f = t*NB + n;
        float zv = g_z2[((size_t)f*P2 + pix)*C2 + c];
        cur = 0.5f*cur + zv;
        vol = 0.5f*vol + cur;
        bool s = (vol >= 1.0f);
        vol = s ? 0.f : vol;
        cnt += s ? 1 : 0;
        uint32_t bal = __ballot_sync(0xffffffffu, s);
        const int p = f*P2 + pix;
        if (s) g_lst2[p*32 + __popc(bal & ltmask)] = (uint8_t)lane;
        if (lane == 0) g_cnt2[p] = (uint8_t)__popc(bal);
    }
    cnt = __reduce_add_sync(0xffffffffu, cnt);
    if (lane == 0) atomicAdd(&g_cnt[1], cnt);
}

// ---- layer 3 conv: thread per (frame, output pixel), f32x2 accumulate ----
__global__ void k_conv3() {
    __shared__ float sW[9*C2*2];
    for (int i = threadIdx.x; i < 9*C2*2; i += blockDim.x) sW[i] = g_w3r[i];
    __syncthreads();
    int idx = blockIdx.x*blockDim.x + threadIdx.x;
    if (idx >= FRAMES*P3) return;
    int ow = idx % W3;
    int oh = (idx / W3) % H3;
    int tn = idx / P3;
    int khs[2], ihs[2], nh; int kws[2], iws[2], nw;
    if (oh & 1) { khs[0]=0; ihs[0]=(oh+1)>>1; khs[1]=2; ihs[1]=(oh-1)>>1; nh=2; }
    else        { khs[0]=1; ihs[0]=oh>>1; nh=1; }
    if (ow & 1) { kws[0]=0; iws[0]=(ow+1)>>1; kws[1]=2; iws[1]=(ow-1)>>1; nw=2; }
    else        { kws[0]=1; iws[0]=ow>>1; nw=1; }
    u64 acc = 0ull;
    for (int a = 0; a < nh; a++)
        for (int b = 0; b < nw; b++) {
            int p = tn*P2 + ihs[a]*W2 + iws[b];
            int c = g_cnt2[p];
            const uint8_t* lp = g_lst2 + p*32;
            const u64* wb = (const u64*)sW + (khs[a]*3 + kws[b])*C2;
            for (int j = 0; j < c; j++) {
                u64 w_ = wb[lp[j]];
                ADD2(acc, w_);
            }
        }
    *(u64*)(g_z3 + (size_t)idx*2) = acc;
}

// ---- final LIF: writes output [N,C,H,W,T]; warp-reduced count ----
__global__ void k_lif3out(float* __restrict__ out) {
    const int idx = blockIdx.x*blockDim.x + threadIdx.x;
    const bool valid = (idx < NB*P3);
    int cnt = 0;
    if (valid) {
        const int pix = idx % P3;
        const int n   = idx / P3;
        const size_t base    = ((size_t)n*P3 + pix)*C3;
        const size_t tstride = (size_t)NB*P3*C3;
        float cur0=0.f, vol0=0.f, cur1=0.f, vol1=0.f;
        float res0[TT], res1[TT];
        #pragma unroll
        for (int t = 0; t < TT; t++) {
            float2 zv = *(const float2*)(g_z3 + (size_t)t*tstride + base);
            cur0 = 0.5f*cur0 + zv.x; vol0 = 0.5f*vol0 + cur0;
            cur1 = 0.5f*cur1 + zv.y; vol1 = 0.5f*vol1 + cur1;
            bool s0 = (vol0 >= 1.0f), s1 = (vol1 >= 1.0f);
            vol0 = s0 ? 0.f : vol0;  vol1 = s1 ? 0.f : vol1;
            res0[t] = s0 ? 1.0f : 0.0f;  res1[t] = s1 ? 1.0f : 0.0f;
            cnt += (s0 ? 1 : 0) + (s1 ? 1 : 0);
        }
        float4* op0 = (float4*)(out + (((size_t)n*C3 + 0)*P3 + pix)*TT);
        float4* op1 = (float4*)(out + (((size_t)n*C3 + 1)*P3 + pix)*TT);
        #pragma unroll
        for (int q = 0; q < 8; q++) {
            op0[q] = make_float4(res0[4*q], res0[4*q+1], res0[4*q+2], res0[4*q+3]);
            op1[q] = make_float4(res1[4*q], res1[4*q+1], res1[4*q+2], res1[4*q+3]);
        }
    }
    cnt = __reduce_add_sync(0xffffffffu, cnt);
    if ((threadIdx.x & 31) == 0 && cnt) atomicAdd(&g_cnt[2], cnt);
}

__global__ void k_final(float* out, int off) {
    if (threadIdx.x == 0) {
        out[off+0] = (float)g_cnt[0] * (1.0f / (float)((size_t)NB*C1*P1*TT));
        out[off+1] = (float)g_cnt[1] * (1.0f / (float)((size_t)NB*C2*P2*TT));
        out[off+2] = (float)g_cnt[2] * (1.0f / (float)((size_t)NB*C3*P3*TT));
    }
}

extern "C" void kernel_launch(void* const* d_in, const int* in_sizes, int n_in,
                              void* d_out, int out_size) {
    const float* x  = (const float*)d_in[0];
    const float* w1 = (const float*)d_in[1];
    const float* w2 = (const float*)d_in[2];
    const float* w3 = (const float*)d_in[3];
    float* out = (float*)d_out;

    const int smem1a = 2*C0*C1*4;   // 65536 (eo/oe; ee uses half)
    const int smem1b = 4*C0*C1*4;   // 131072 (oo)
    const int smem2  = 4*C1*C2*4;   // 32768 (oo class max)
    cudaFuncSetAttribute((const void*)k_conv1a,
                         cudaFuncAttributeMaxDynamicSharedMemorySize, smem1a);
    cudaFuncSetAttribute((const void*)k_conv1b,
                         cudaFuncAttributeMaxDynamicSharedMemorySize, smem1b);

    const int wtot = 9*C0*C1 + 9*C1*C2 + 9*C2*C3;
    k_prep<<<NB*P0 + (wtot + 127)/128, 128>>>(x, w1, w2, w3);
    k_conv1a<<<296, 1024, smem1a>>>();
    k_conv1b<<<148, 1024, smem1b>>>();
    k_lif1<<<961, 128>>>();
    k_conv2<<<296, 1024, smem2>>>();
    k_lif2<<<(NB*P2*C2 + 255)/256, 256>>>();
    k_conv3<<<(FRAMES*P3 + 255)/256, 256>>>();
    k_lif3out<<<(NB*P3 + 255)/256, 256>>>(out);
    k_final<<<1, 32>>>(out, out_size - 3);
}